// round 8
// baseline (speedup 1.0000x reference)
#include <cuda_runtime.h>
#include <cuda_bf16.h>
#include <cstdint>

// BNB 8-bit embedding dequant-on-gather (sm_103a), R8.
// Identities: row base = q_idx + id*1024; scale = absmax[id>>2].
//
// Read path = R7 (best): 8 tokens/CTA, 256 threads in two 128-lane halves,
// 4 front-batched LDG.256 per thread. NEW write path: dequant into a 32KB
// smem staging buffer, then ONE cp.async.bulk shared->global per CTA
// (per-CTA output is contiguous: 8 consecutive token rows). Replaces 1024
// scattered STG.256 with a single clean 32KB DRAM write burst.

#define TOKENS_PER_CTA 8
#define ROW_F 1024

__device__ __forceinline__ uint32_t smem_u32(const void* p) {
    uint32_t a;
    asm("{ .reg .u64 t; cvta.to.shared.u64 t, %1; cvt.u32.u64 %0, t; }"
        : "=r"(a) : "l"(p));
    return a;
}

__device__ __forceinline__ void ldg_nc_el_v8(const int* p, uint32_t r[8]) {
    asm volatile("ld.global.nc.L2::evict_last.v8.b32 "
                 "{%0,%1,%2,%3,%4,%5,%6,%7}, [%8];"
                 : "=r"(r[0]), "=r"(r[1]), "=r"(r[2]), "=r"(r[3]),
                   "=r"(r[4]), "=r"(r[5]), "=r"(r[6]), "=r"(r[7])
                 : "l"(p));
}

__global__ __launch_bounds__(256)
void bnb8bit_embedding_kernel(const int* __restrict__ x,
                              const int* __restrict__ q_idx,
                              const float* __restrict__ absmax,
                              const float* __restrict__ code,
                              float* __restrict__ out,
                              int n_tokens) {
    __shared__ float s_code[256];
    __shared__ int   s_ids[TOKENS_PER_CTA];
    __shared__ __align__(128) float s_out[TOKENS_PER_CTA * ROW_F];  // 32 KB

    const int t = threadIdx.x;
    s_code[t] = code[t];

    const int base   = blockIdx.x * TOKENS_PER_CTA;
    const int nvalid = min(TOKENS_PER_CTA, n_tokens - base);

    if (t < TOKENS_PER_CTA) {
        int tok = base + t;
        s_ids[t] = (t < nvalid) ? x[tok] : 0;
    }
    __syncthreads();

    const int half = t >> 7;        // which group of 4 tokens
    const int lane = t & 127;       // 32B segment within the row
    const int toff = half * 4;

    if (nvalid == TOKENS_PER_CTA) {
        uint32_t v[4][8];
        float    sc[4];
        #pragma unroll
        for (int i = 0; i < 4; i++) {
            const int id = s_ids[toff + i];
            sc[i] = __ldg(absmax + (id >> 2));
            ldg_nc_el_v8(q_idx + (size_t)id * ROW_F + lane * 8, v[i]);
        }
        #pragma unroll
        for (int i = 0; i < 4; i++) {
            float4* sp = reinterpret_cast<float4*>(&s_out[(toff + i) * ROW_F + lane * 8]);
            float4 a, b;
            a.x = s_code[v[i][0]] * sc[i];  a.y = s_code[v[i][1]] * sc[i];
            a.z = s_code[v[i][2]] * sc[i];  a.w = s_code[v[i][3]] * sc[i];
            b.x = s_code[v[i][4]] * sc[i];  b.y = s_code[v[i][5]] * sc[i];
            b.z = s_code[v[i][6]] * sc[i];  b.w = s_code[v[i][7]] * sc[i];
            sp[0] = a;
            sp[1] = b;
        }
    } else {
        for (int i = 0; i < 4; i++) {
            if (toff + i >= nvalid) break;
            const int id = s_ids[toff + i];
            const float sc = __ldg(absmax + (id >> 2));
            uint32_t v[8];
            ldg_nc_el_v8(q_idx + (size_t)id * ROW_F + lane * 8, v);
            float4* sp = reinterpret_cast<float4*>(&s_out[(toff + i) * ROW_F + lane * 8]);
            float4 a, b;
            a.x = s_code[v[0]] * sc;  a.y = s_code[v[1]] * sc;
            a.z = s_code[v[2]] * sc;  a.w = s_code[v[3]] * sc;
            b.x = s_code[v[4]] * sc;  b.y = s_code[v[5]] * sc;
            b.z = s_code[v[6]] * sc;  b.w = s_code[v[7]] * sc;
            sp[0] = a;
            sp[1] = b;
        }
    }

    __syncthreads();   // staging buffer complete

    if (t == 0) {
        // Generic-proxy smem writes must be visible to the async proxy.
        asm volatile("fence.proxy.async.shared::cta;" ::: "memory");
        asm volatile(
            "cp.async.bulk.global.shared::cta.bulk_group [%0], [%1], %2;"
            :: "l"(out + (size_t)base * ROW_F),
               "r"(smem_u32(s_out)),
               "r"((uint32_t)(nvalid * ROW_F * 4))
            : "memory");
        asm volatile("cp.async.bulk.commit_group;" ::: "memory");
        // smem must stay valid until the bulk store drains.
        asm volatile("cp.async.bulk.wait_group 0;" ::: "memory");
    }
}

extern "C" void kernel_launch(void* const* d_in, const int* in_sizes, int n_in,
                              void* d_out, int out_size) {
    const int*   x      = (const int*)d_in[0];
    const int*   q_idx  = (const int*)d_in[1];
    const float* absmax = (const float*)d_in[2];
    const float* code   = (const float*)d_in[3];
    float*       out    = (float*)d_out;

    const int n_tokens = in_sizes[0];   // 8*4096 = 32768
    const int grid = (n_tokens + TOKENS_PER_CTA - 1) / TOKENS_PER_CTA;
    bnb8bit_embedding_kernel<<<grid, 256>>>(x, q_idx, absmax, code, out, n_tokens);
}

// round 9
// speedup vs baseline: 1.0088x; 1.0088x over previous
#include <cuda_runtime.h>
#include <cuda_bf16.h>
#include <cstdint>

// BNB 8-bit embedding dequant-on-gather (sm_103a), R9: persistent grid-stride.
// Identities: row base = q_idx + id*1024; scale = absmax[id>>2].
//
// 1184 persistent CTAs (256 threads, two 128-lane halves) loop over 8-token
// batches. Per iteration: each half broadcast-loads its 4 ids (one int4),
// then 4 front-batched LDG.256 + 4 STG.256 per thread. No smem id staging,
// no in-loop __syncthreads -> iteration k+1 loads overlap iteration k stores.

#define TPB 8          // tokens per batch
#define ROW_F 1024

__device__ __forceinline__ void ldg_nc_el_v8(const int* p, uint32_t r[8]) {
    asm volatile("ld.global.nc.L2::evict_last.v8.b32 "
                 "{%0,%1,%2,%3,%4,%5,%6,%7}, [%8];"
                 : "=r"(r[0]), "=r"(r[1]), "=r"(r[2]), "=r"(r[3]),
                   "=r"(r[4]), "=r"(r[5]), "=r"(r[6]), "=r"(r[7])
                 : "l"(p));
}

__device__ __forceinline__ void stg_cs_v8(float* p, const float o[8]) {
    asm volatile("st.global.cs.v8.f32 [%0], {%1,%2,%3,%4,%5,%6,%7,%8};"
                 :: "l"(p),
                    "f"(o[0]), "f"(o[1]), "f"(o[2]), "f"(o[3]),
                    "f"(o[4]), "f"(o[5]), "f"(o[6]), "f"(o[7])
                 : "memory");
}

__global__ __launch_bounds__(256)
void bnb8bit_embedding_kernel(const int* __restrict__ x,
                              const int* __restrict__ q_idx,
                              const float* __restrict__ absmax,
                              const float* __restrict__ code,
                              float* __restrict__ out,
                              int n_tokens) {
    __shared__ float s_code[256];
    const int t = threadIdx.x;
    s_code[t] = code[t];
    __syncthreads();   // once per CTA

    const int half = t >> 7;        // which group of 4 tokens in the batch
    const int lane = t & 127;       // 32B segment within a row
    const int n_batches = (n_tokens + TPB - 1) / TPB;

    for (int batch = blockIdx.x; batch < n_batches; batch += gridDim.x) {
        const int base = batch * TPB;

        if (base + TPB <= n_tokens) {
            // Each half loads its own 4 ids: one aligned int4, broadcast
            // within the half (same address across 128 lanes).
            const int4 ids = __ldg(reinterpret_cast<const int4*>(x + base) + half);
            const int id[4] = {ids.x, ids.y, ids.z, ids.w};

            uint32_t v[4][8];
            float    sc[4];
            #pragma unroll
            for (int i = 0; i < 4; i++) {
                sc[i] = __ldg(absmax + (id[i] >> 2));
                ldg_nc_el_v8(q_idx + (size_t)id[i] * ROW_F + lane * 8, v[i]);
            }
            #pragma unroll
            for (int i = 0; i < 4; i++) {
                float o[8];
                #pragma unroll
                for (int j = 0; j < 8; j++)
                    o[j] = s_code[v[i][j]] * sc[i];
                stg_cs_v8(out + (size_t)(base + half * 4 + i) * ROW_F + lane * 8, o);
            }
        } else {
            // Tail batch.
            for (int i = 0; i < 4; i++) {
                const int tok = base + half * 4 + i;
                if (tok >= n_tokens) continue;
                const int idt = __ldg(x + tok);
                const float sc = __ldg(absmax + (idt >> 2));
                uint32_t v[8];
                ldg_nc_el_v8(q_idx + (size_t)idt * ROW_F + lane * 8, v);
                float o[8];
                #pragma unroll
                for (int j = 0; j < 8; j++)
                    o[j] = s_code[v[j]] * sc;
                stg_cs_v8(out + (size_t)tok * ROW_F + lane * 8, o);
            }
        }
    }
}

extern "C" void kernel_launch(void* const* d_in, const int* in_sizes, int n_in,
                              void* d_out, int out_size) {
    const int*   x      = (const int*)d_in[0];
    const int*   q_idx  = (const int*)d_in[1];
    const float* absmax = (const float*)d_in[2];
    const float* code   = (const float*)d_in[3];
    float*       out    = (float*)d_out;

    const int n_tokens = in_sizes[0];       // 8*4096 = 32768
    const int n_batches = (n_tokens + TPB - 1) / TPB;
    int grid = 148 * 8;                     // persistent: ~8 CTAs/SM
    if (grid > n_batches) grid = n_batches;
    bnb8bit_embedding_kernel<<<grid, 256>>>(x, q_idx, absmax, code, out, n_tokens);
}